// round 12
// baseline (speedup 1.0000x reference)
#include <cuda_runtime.h>
#include <cuda_bf16.h>
#include <math.h>

#define NSAMP 32768
#define PPERM 32
typedef unsigned long long u64;
typedef unsigned int u32;

// ---------------- scratch ----------------
__device__ float g_sc2[25];
__device__ u64 g_W0[PPERM * 25];
__device__ __align__(16) unsigned short g_Wf[PPERM * 28672]; // B-fragment table 57344 B/perm
__device__ float g_pm[PPERM * NSAMP];
__device__ float g_pv[PPERM * NSAMP];

__device__ __constant__ float BINC[25] = {
    1.f, 24.f, 276.f, 2024.f, 10626.f, 42504.f, 134596.f, 346104.f,
    735471.f, 1307504.f, 1961256.f, 2496144.f, 2704156.f, 2496144.f,
    1961256.f, 1307504.f, 735471.f, 346104.f, 134596.f, 42504.f,
    10626.f, 2024.f, 276.f, 24.f, 1.f};

// ---------------- helpers ----------------
__device__ __forceinline__ void mma16816(float d[4], const u32 a[4], u32 b0, u32 b1) {
    asm volatile("mma.sync.aligned.m16n8k16.row.col.f32.bf16.bf16.f32 "
        "{%0,%1,%2,%3}, {%4,%5,%6,%7}, {%8,%9}, {%0,%1,%2,%3};"
        : "+f"(d[0]), "+f"(d[1]), "+f"(d[2]), "+f"(d[3])
        : "r"(a[0]), "r"(a[1]), "r"(a[2]), "r"(a[3]), "r"(b0), "r"(b1));
}
__device__ __forceinline__ void lds64(u32& a, u32& b, u32 addr) {
    asm("ld.shared.v2.u32 {%0, %1}, [%2];" : "=r"(a), "=r"(b) : "r"(addr));
}
__device__ __forceinline__ void split_pack(float e0, float e1, u32& hi, u32& lo) {
    u32 h;
    asm("cvt.rn.bf16x2.f32 %0, %1, %2;" : "=r"(h) : "f"(e1), "f"(e0));
    float h0 = __uint_as_float(h << 16);
    float h1 = __uint_as_float(h & 0xffff0000u);
    asm("cvt.rn.bf16x2.f32 %0, %1, %2;" : "=r"(lo) : "f"(e1 - h1), "f"(e0 - h0));
    hi = h;
}
// s[2nt+c] = u^j (1-u)^(24-j) for j = 8nt + 2tg + c; j>24 -> 0. Division-free.
__device__ __forceinline__ void scales8(float u, int tg, float s[8]) {
    float om = 1.0f - u;
    float u2 = u * u, u4 = u2 * u2, u8 = u4 * u4, u16 = u8 * u8;
    float om2 = om * om, om4 = om2 * om2, om8 = om4 * om4, om16 = om8 * om8;
    float ut = ((tg & 1) ? u2 : 1.0f) * ((tg & 2) ? u4 : 1.0f);      // u^{2tg}
    int q = 4 - tg;
    float C0 = ((q & 1) ? om2 : 1.0f) * ((q & 2) ? om4 : 1.0f) * ((q & 4) ? om8 : 1.0f);
    int r = 3 - tg;
    float C1 = om * ((r & 1) ? om2 : 1.0f) * ((r & 2) ? om4 : 1.0f);
    float U0 = ut, U1 = ut * u;
    s[0] = U0 * (C0 * om16);
    s[1] = U1 * (C1 * om16);
    s[2] = (U0 * u8) * (C0 * om8);
    s[3] = (U1 * u8) * (C1 * om8);
    s[4] = (U0 * u16) * C0;
    s[5] = (U1 * u16) * C1;
    s[6] = (tg == 0) ? (u16 * u8) : 0.0f;
    s[7] = 0.0f;
}

// ---------------- setup: sc2 ----------------
__global__ void k_sc2() {
    __shared__ double A[25][26];
    __shared__ int piv;
    int t = threadIdx.x;
    if (t < 25) {
        float ti = (float)t / 24.0f, om = 1.0f - ti;
        for (int k = 0; k < 25; k++) {
            float xk = (float)pow((double)ti, (double)k);
            float ym = (float)pow((double)om, (double)(24 - k));
            float val = (xk * ym) * BINC[k];
            A[t][k] = (double)(val * val);
        }
        A[t][25] = 1.0;
    }
    __syncthreads();
    for (int k = 0; k < 25; k++) {
        if (t == 0) {
            int pi = k; double best = fabs(A[k][k]);
            for (int i = k + 1; i < 25; i++) { double v = fabs(A[i][k]); if (v > best) { best = v; pi = i; } }
            piv = pi;
        }
        __syncthreads();
        int pv = piv;
        if (pv != k && t < 26) { double tmp = A[k][t]; A[k][t] = A[pv][t]; A[pv][t] = tmp; }
        __syncthreads();
        if (t < 25 && t != k) {
            double f = A[t][k] / A[k][k];
            for (int j = k; j < 26; j++) A[t][j] -= f * A[k][j];
        }
        __syncthreads();
    }
    if (t < 25) g_sc2[t] = (float)(A[t][25] / A[t][t]);
}

// ---------------- prep: B fragments ----------------
__global__ void k_prep_frag(const float* __restrict__ wmr, const float* __restrict__ wvr) {
    int idx = blockIdx.x * blockDim.x + threadIdx.x;
    if (idx >= PPERM * 28672) return;
    int p = idx / 28672;  int r  = idx - p * 28672;
    int l = r / 4096;     int r2 = r - l * 4096;
    int path = r2 / 2048; int r3 = r2 - path * 2048;
    int split = r3 / 1024; int r4 = r3 - split * 1024;
    int ks = r4 / 512;    int r5 = r4 - ks * 512;
    int nt = r5 / 128;    int r6 = r5 - nt * 128;
    int t = r6 / 4,       e = r6 - t * 4;
    int k = 16 * ks + 2 * (t & 3) + (e & 1) + 8 * (e >> 1);
    int j = 8 * nt + (t >> 2);
    float v = 0.0f;
    if (k < 25 && j < 25) {
        int src = ((l * 32 + p) * 25 + k) * 25 + j;
        v = (path == 0) ? wmr[src] * BINC[j]
                        : expf(wvr[src]) * g_sc2[j] * BINC[j] * BINC[j];
    }
    __nv_bfloat16 h = __float2bfloat16(v);
    g_Wf[idx] = (split == 0) ? __bfloat16_as_ushort(h)
                             : __bfloat16_as_ushort(__float2bfloat16(v - __bfloat162float(h)));
}

__global__ void k_prep0(const float* __restrict__ wm0, const float* __restrict__ wv0) {
    int i = blockIdx.x * blockDim.x + threadIdx.x;
    if (i >= PPERM * 25) return;
    int p = i / 25, j = i - p * 25;
    float b = BINC[j];
    float lo = wm0[p * 25 + j] * b;
    float hi = expf(wv0[p * 25 + j]) * g_sc2[j] * b * b;
    g_W0[i] = ((u64)__float_as_uint(hi) << 32) | (u64)__float_as_uint(lo);
}

// ---------------- main: chained HMMA, warp = 2 x 16-sample tiles ----------------
// Two tiles per warp: B fragments loaded once feed both tiles' MMAs (LDS/sample
// halves) and tile-1's 24 in-flight MMAs cover tile-0's epilogue (intra-warp
// tensor/CUDA-core overlap independent of warp phasing).
__global__ void __launch_bounds__(128, 2) k_main(
    const float* __restrict__ X, const int* __restrict__ perm,
    const float* __restrict__ pprec)
{
    extern __shared__ __align__(16) unsigned short sWf[];   // 57344 B
    __shared__ float2 s0[32];
    __shared__ int sperm[8];

    int p = blockIdx.y;
    int tid = threadIdx.x;
    {
        const float4* src = (const float4*)(g_Wf + (size_t)p * 28672);
        float4* dst = (float4*)sWf;
        #pragma unroll
        for (int i = 0; i < 3584; i += 128) dst[i + tid] = src[i + tid];
    }
    if (tid < 32) s0[tid] = (tid < 25) ? *(const float2*)&g_W0[p * 25 + tid] : make_float2(0.f, 0.f);
    if (tid < 8)  sperm[tid] = perm[p * 8 + tid];
    __syncthreads();

    int lane = tid & 31, w = tid >> 5;
    int tg = lane & 3, g = lane >> 2;
    u32 wbase = (u32)__cvta_generic_to_shared(sWf) + (u32)(lane * 8);
    float invp = 1.0f / __ldg(pprec + p);

    #pragma unroll 1
    for (int tp = 0; tp < 4; tp++) {
        int nbase = blockIdx.x * 512 + w * 128 + tp * 32;
        int na[2] = { nbase + g, nbase + 16 + g };            // row g of each tile
        const float* xa[2] = { X + (size_t)na[0] * 8, X + (size_t)na[1] * 8 };
        const float* xb[2] = { xa[0] + 64, xa[1] + 64 };      // row g+8 = na+8

        u32 Amh[2][2][4], Aml[2][2][4], Avh[2][2][4], Avl[2][2][4];  // [tile][ks][reg]
        float sa[2][8], sb[2][8];

        // ---- level 0 init (both tiles) ----
        #pragma unroll
        for (int t = 0; t < 2; t++) {
            scales8(__ldg(xa[t] + sperm[0]), tg, sa[t]);
            scales8(__ldg(xb[t] + sperm[0]), tg, sb[t]);
            #pragma unroll
            for (int ks = 0; ks < 2; ks++)
            #pragma unroll
            for (int h = 0; h < 2; h++) {
                int nt = 2 * ks + h;
                float2 w0 = s0[8 * nt + 2 * tg];
                float2 w1 = s0[8 * nt + 2 * tg + 1];
                float s0a = sa[t][2 * nt], s1a = sa[t][2 * nt + 1];
                float s0b = sb[t][2 * nt], s1b = sb[t][2 * nt + 1];
                split_pack(w0.x * s0a, w1.x * s1a, Amh[t][ks][2 * h],     Aml[t][ks][2 * h]);
                split_pack(w0.x * s0b, w1.x * s1b, Amh[t][ks][2 * h + 1], Aml[t][ks][2 * h + 1]);
                split_pack(w0.y * s0a * s0a, w1.y * s1a * s1a, Avh[t][ks][2 * h],     Avl[t][ks][2 * h]);
                split_pack(w0.y * s0b * s0b, w1.y * s1b * s1b, Avh[t][ks][2 * h + 1], Avl[t][ks][2 * h + 1]);
            }
        }

        // ---- levels 1..7 ----
        #pragma unroll 1
        for (int l = 1; l <= 7; l++) {
            float Dm[2][4][4] = {}, Dv[2][4][4] = {};
            u32 lb = wbase + (u32)((l - 1) * 8192);
            #pragma unroll
            for (int nt = 0; nt < 4; nt++) {
                u32 o = lb + (u32)(nt * 256);
                u32 h00, h01, h10, h11, l00, l01, l10, l11;
                lds64(h00, h01, o);           lds64(h10, h11, o + 1024);
                lds64(l00, l01, o + 2048);    lds64(l10, l11, o + 3072);
                #pragma unroll
                for (int t = 0; t < 2; t++) {
                    mma16816(Dm[t][nt], Amh[t][0], h00, h01);
                    mma16816(Dm[t][nt], Amh[t][1], h10, h11);
                    mma16816(Dm[t][nt], Amh[t][0], l00, l01);
                    mma16816(Dm[t][nt], Amh[t][1], l10, l11);
                    mma16816(Dm[t][nt], Aml[t][0], h00, h01);
                    mma16816(Dm[t][nt], Aml[t][1], h10, h11);
                }
                lds64(h00, h01, o + 4096);    lds64(h10, h11, o + 5120);
                lds64(l00, l01, o + 6144);    lds64(l10, l11, o + 7168);
                #pragma unroll
                for (int t = 0; t < 2; t++) {
                    mma16816(Dv[t][nt], Avh[t][0], h00, h01);
                    mma16816(Dv[t][nt], Avh[t][1], h10, h11);
                    mma16816(Dv[t][nt], Avh[t][0], l00, l01);
                    mma16816(Dv[t][nt], Avh[t][1], l10, l11);
                    mma16816(Dv[t][nt], Avl[t][0], h00, h01);
                    mma16816(Dv[t][nt], Avl[t][1], h10, h11);
                }
            }
            // epilogues (tile 0 first: its D is oldest; tile 1's MMAs cover it)
            #pragma unroll
            for (int t = 0; t < 2; t++) {
                scales8(__ldg(xa[t] + sperm[l]), tg, sa[t]);
                scales8(__ldg(xb[t] + sperm[l]), tg, sb[t]);
                if (l < 7) {
                    #pragma unroll
                    for (int ks = 0; ks < 2; ks++)
                    #pragma unroll
                    for (int h = 0; h < 2; h++) {
                        int nt = 2 * ks + h;
                        float s0a = sa[t][2 * nt], s1a = sa[t][2 * nt + 1];
                        float s0b = sb[t][2 * nt], s1b = sb[t][2 * nt + 1];
                        split_pack(Dm[t][nt][0] * s0a, Dm[t][nt][1] * s1a, Amh[t][ks][2 * h],     Aml[t][ks][2 * h]);
                        split_pack(Dm[t][nt][2] * s0b, Dm[t][nt][3] * s1b, Amh[t][ks][2 * h + 1], Aml[t][ks][2 * h + 1]);
                        split_pack(Dv[t][nt][0] * s0a * s0a, Dv[t][nt][1] * s1a * s1a, Avh[t][ks][2 * h],     Avl[t][ks][2 * h]);
                        split_pack(Dv[t][nt][2] * s0b * s0b, Dv[t][nt][3] * s1b * s1b, Avh[t][ks][2 * h + 1], Avl[t][ks][2 * h + 1]);
                    }
                } else {
                    float smA = 0.f, smB = 0.f, svA = 0.f, svB = 0.f;
                    #pragma unroll
                    for (int nt = 0; nt < 4; nt++) {
                        float s0a = sa[t][2 * nt], s1a = sa[t][2 * nt + 1];
                        float s0b = sb[t][2 * nt], s1b = sb[t][2 * nt + 1];
                        smA += Dm[t][nt][0] * s0a + Dm[t][nt][1] * s1a;
                        smB += Dm[t][nt][2] * s0b + Dm[t][nt][3] * s1b;
                        svA += Dv[t][nt][0] * (s0a * s0a) + Dv[t][nt][1] * (s1a * s1a);
                        svB += Dv[t][nt][2] * (s0b * s0b) + Dv[t][nt][3] * (s1b * s1b);
                    }
                    smA += __shfl_xor_sync(0xffffffff, smA, 1); smA += __shfl_xor_sync(0xffffffff, smA, 2);
                    smB += __shfl_xor_sync(0xffffffff, smB, 1); smB += __shfl_xor_sync(0xffffffff, smB, 2);
                    svA += __shfl_xor_sync(0xffffffff, svA, 1); svA += __shfl_xor_sync(0xffffffff, svA, 2);
                    svB += __shfl_xor_sync(0xffffffff, svB, 1); svB += __shfl_xor_sync(0xffffffff, svB, 2);
                    if (tg == 0) {
                        g_pm[p * NSAMP + na[t]] = smA;
                        g_pv[p * NSAMP + na[t]] = svA * invp;
                        g_pm[p * NSAMP + na[t] + 8] = smB;
                        g_pv[p * NSAMP + na[t] + 8] = svB * invp;
                    }
                }
            }
        }
    }
}

// ---------------- reduction over permutations ----------------
__global__ void k_reduce(float* __restrict__ out) {
    int n = blockIdx.x * blockDim.x + threadIdx.x;
    float sm = 0.f, sv = 0.f;
    #pragma unroll
    for (int p = 0; p < PPERM; p++) {
        sm += g_pm[p * NSAMP + n];
        sv += g_pv[p * NSAMP + n];
    }
    out[2 * n]     = sm;
    out[2 * n + 1] = sv;
}

extern "C" void kernel_launch(void* const* d_in, const int* in_sizes, int n_in,
                              void* d_out, int out_size) {
    const float* X    = (const float*)d_in[0];
    const int*   perm = (const int*)  d_in[1];
    const float* wm0  = (const float*)d_in[2];
    const float* wmr  = (const float*)d_in[3];
    const float* wv0  = (const float*)d_in[4];
    const float* wvr  = (const float*)d_in[5];
    const float* pp   = (const float*)d_in[6];

    cudaFuncSetAttribute(k_main, cudaFuncAttributeMaxDynamicSharedMemorySize, 57344);
    // launch index 3 = k_main (ncu captures the 4th launch)
    k_sc2<<<1, 32>>>();
    k_prep_frag<<<(PPERM * 28672 + 255) / 256, 256>>>(wmr, wvr);
    k_prep0<<<(PPERM * 25 + 255) / 256, 256>>>(wm0, wv0);
    k_main<<<dim3(64, 32), 128, 57344>>>(X, perm, pp);
    k_reduce<<<NSAMP / 256, 256>>>((float*)d_out);
}

// round 15
// speedup vs baseline: 1.0002x; 1.0002x over previous
#include <cuda_runtime.h>
#include <cuda_bf16.h>
#include <math.h>

#define NSAMP 32768
#define PPERM 32
typedef unsigned long long u64;
typedef unsigned int u32;

// ---------------- scratch ----------------
__device__ float g_sc2[25];
__device__ u64 g_W0[PPERM * 25];
__device__ __align__(16) unsigned short g_Wf[PPERM * 28672]; // B-fragment table 57344 B/perm
__device__ float g_pm[PPERM * NSAMP];
__device__ float g_pv[PPERM * NSAMP];

__device__ __constant__ float BINC[25] = {
    1.f, 24.f, 276.f, 2024.f, 10626.f, 42504.f, 134596.f, 346104.f,
    735471.f, 1307504.f, 1961256.f, 2496144.f, 2704156.f, 2496144.f,
    1961256.f, 1307504.f, 735471.f, 346104.f, 134596.f, 42504.f,
    10626.f, 2024.f, 276.f, 24.f, 1.f};

// ---------------- helpers ----------------
__device__ __forceinline__ void mma16816(float d[4], const u32 a[4], u32 b0, u32 b1) {
    asm volatile("mma.sync.aligned.m16n8k16.row.col.f32.bf16.bf16.f32 "
        "{%0,%1,%2,%3}, {%4,%5,%6,%7}, {%8,%9}, {%0,%1,%2,%3};"
        : "+f"(d[0]), "+f"(d[1]), "+f"(d[2]), "+f"(d[3])
        : "r"(a[0]), "r"(a[1]), "r"(a[2]), "r"(a[3]), "r"(b0), "r"(b1));
}
__device__ __forceinline__ void lds64(u32& a, u32& b, u32 addr) {
    asm("ld.shared.v2.u32 {%0, %1}, [%2];" : "=r"(a), "=r"(b) : "r"(addr));
}
__device__ __forceinline__ void split_pack(float e0, float e1, u32& hi, u32& lo) {
    u32 h;
    asm("cvt.rn.bf16x2.f32 %0, %1, %2;" : "=r"(h) : "f"(e1), "f"(e0));
    float h0 = __uint_as_float(h << 16);
    float h1 = __uint_as_float(h & 0xffff0000u);
    asm("cvt.rn.bf16x2.f32 %0, %1, %2;" : "=r"(lo) : "f"(e1 - h1), "f"(e0 - h0));
    hi = h;
}
// s[2nt+c] = u^j (1-u)^(24-j) for j = 8nt + 2tg + c; j>24 -> 0. Division-free.
__device__ __forceinline__ void scales8(float u, int tg, float s[8]) {
    float om = 1.0f - u;
    float u2 = u * u, u4 = u2 * u2, u8 = u4 * u4, u16 = u8 * u8;
    float om2 = om * om, om4 = om2 * om2, om8 = om4 * om4, om16 = om8 * om8;
    float ut = ((tg & 1) ? u2 : 1.0f) * ((tg & 2) ? u4 : 1.0f);
    int q = 4 - tg;
    float C0 = ((q & 1) ? om2 : 1.0f) * ((q & 2) ? om4 : 1.0f) * ((q & 4) ? om8 : 1.0f);
    int r = 3 - tg;
    float C1 = om * ((r & 1) ? om2 : 1.0f) * ((r & 2) ? om4 : 1.0f);
    float U0 = ut, U1 = ut * u;
    s[0] = U0 * (C0 * om16);
    s[1] = U1 * (C1 * om16);
    s[2] = (U0 * u8) * (C0 * om8);
    s[3] = (U1 * u8) * (C1 * om8);
    s[4] = (U0 * u16) * C0;
    s[5] = (U1 * u16) * C1;
    s[6] = (tg == 0) ? (u16 * u8) : 0.0f;
    s[7] = 0.0f;
}
// issue 24 MMAs for one path; lb = per-lane base addr of this path's fragments
__device__ __forceinline__ void issue_path(u32 lb, const u32 Ah[2][4], const u32 Al[2][4],
                                           float D[4][4]) {
    #pragma unroll
    for (int nt = 0; nt < 4; nt++) {
        u32 o = lb + (u32)(nt * 256);
        u32 h00, h01, h10, h11, l00, l01, l10, l11;
        lds64(h00, h01, o);         lds64(h10, h11, o + 1024);
        lds64(l00, l01, o + 2048);  lds64(l10, l11, o + 3072);
        D[nt][0] = D[nt][1] = D[nt][2] = D[nt][3] = 0.f;
        mma16816(D[nt], Ah[0], h00, h01);
        mma16816(D[nt], Ah[1], h10, h11);
        mma16816(D[nt], Ah[0], l00, l01);
        mma16816(D[nt], Ah[1], l10, l11);
        mma16816(D[nt], Al[0], h00, h01);
        mma16816(D[nt], Al[1], h10, h11);
    }
}

// ---------------- setup: sc2 ----------------
__global__ void k_sc2() {
    __shared__ double A[25][26];
    __shared__ int piv;
    int t = threadIdx.x;
    if (t < 25) {
        float ti = (float)t / 24.0f, om = 1.0f - ti;
        for (int k = 0; k < 25; k++) {
            float xk = (float)pow((double)ti, (double)k);
            float ym = (float)pow((double)om, (double)(24 - k));
            float val = (xk * ym) * BINC[k];
            A[t][k] = (double)(val * val);
        }
        A[t][25] = 1.0;
    }
    __syncthreads();
    for (int k = 0; k < 25; k++) {
        if (t == 0) {
            int pi = k; double best = fabs(A[k][k]);
            for (int i = k + 1; i < 25; i++) { double v = fabs(A[i][k]); if (v > best) { best = v; pi = i; } }
            piv = pi;
        }
        __syncthreads();
        int pv = piv;
        if (pv != k && t < 26) { double tmp = A[k][t]; A[k][t] = A[pv][t]; A[pv][t] = tmp; }
        __syncthreads();
        if (t < 25 && t != k) {
            double f = A[t][k] / A[k][k];
            for (int j = k; j < 26; j++) A[t][j] -= f * A[k][j];
        }
        __syncthreads();
    }
    if (t < 25) g_sc2[t] = (float)(A[t][25] / A[t][t]);
}

// ---------------- prep: B fragments ----------------
__global__ void k_prep_frag(const float* __restrict__ wmr, const float* __restrict__ wvr) {
    int idx = blockIdx.x * blockDim.x + threadIdx.x;
    if (idx >= PPERM * 28672) return;
    int p = idx / 28672;  int r  = idx - p * 28672;
    int l = r / 4096;     int r2 = r - l * 4096;
    int path = r2 / 2048; int r3 = r2 - path * 2048;
    int split = r3 / 1024; int r4 = r3 - split * 1024;
    int ks = r4 / 512;    int r5 = r4 - ks * 512;
    int nt = r5 / 128;    int r6 = r5 - nt * 128;
    int t = r6 / 4,       e = r6 - t * 4;
    int k = 16 * ks + 2 * (t & 3) + (e & 1) + 8 * (e >> 1);
    int j = 8 * nt + (t >> 2);
    float v = 0.0f;
    if (k < 25 && j < 25) {
        int src = ((l * 32 + p) * 25 + k) * 25 + j;
        v = (path == 0) ? wmr[src] * BINC[j]
                        : expf(wvr[src]) * g_sc2[j] * BINC[j] * BINC[j];
    }
    __nv_bfloat16 h = __float2bfloat16(v);
    g_Wf[idx] = (split == 0) ? __bfloat16_as_ushort(h)
                             : __bfloat16_as_ushort(__float2bfloat16(v - __bfloat162float(h)));
}

__global__ void k_prep0(const float* __restrict__ wm0, const float* __restrict__ wv0) {
    int i = blockIdx.x * blockDim.x + threadIdx.x;
    if (i >= PPERM * 25) return;
    int p = i / 25, j = i - p * 25;
    float b = BINC[j];
    float lo = wm0[p * 25 + j] * b;
    float hi = expf(wv0[p * 25 + j]) * g_sc2[j] * b * b;
    g_W0[i] = ((u64)__float_as_uint(hi) << 32) | (u64)__float_as_uint(lo);
}

// ---------------- main: chained HMMA with staggered mean/var pipeline ----------------
// Per level: issue var MMAs, run mean epilogue under them, issue next mean MMAs,
// run var epilogue under those. Every epilogue overlaps 24 in-flight MMAs of the
// other path — guaranteed intra-warp tensor/CUDA-core overlap.
__global__ void __launch_bounds__(256, 2) k_main(
    const float* __restrict__ X, const int* __restrict__ perm,
    const float* __restrict__ pprec)
{
    extern __shared__ __align__(16) unsigned short sWf[];   // 57344 B
    __shared__ float2 s0[32];
    __shared__ int sperm[8];

    int p = blockIdx.y;
    int tid = threadIdx.x;
    {
        const float4* src = (const float4*)(g_Wf + (size_t)p * 28672);
        float4* dst = (float4*)sWf;
        #pragma unroll
        for (int i = 0; i < 3584; i += 256) dst[i + tid] = src[i + tid];
    }
    if (tid < 32) s0[tid] = (tid < 25) ? *(const float2*)&g_W0[p * 25 + tid] : make_float2(0.f, 0.f);
    if (tid < 8)  sperm[tid] = perm[p * 8 + tid];
    __syncthreads();

    int lane = tid & 31, w = tid >> 5;
    int tg = lane & 3, g = lane >> 2;
    u32 wbase = (u32)__cvta_generic_to_shared(sWf) + (u32)(lane * 8);
    float invp = 1.0f / __ldg(pprec + p);

    #pragma unroll 1
    for (int tt = 0; tt < 8; tt++) {
        int na = (blockIdx.x * 8 + tt) * 128 + w * 16 + g;   // row g
        int nb = na + 8;                                      // row g+8
        const float* xa = X + (size_t)na * 8;
        const float* xb = X + (size_t)nb * 8;

        u32 Amh[2][4], Aml[2][4], Avh[2][4], Avl[2][4];
        float Dm[4][4], Dv[4][4];
        float sa[8], sb[8];
        float smA, smB;                                       // final mean partials

        // ---- level 0 init ----
        scales8(__ldg(xa + sperm[0]), tg, sa);
        scales8(__ldg(xb + sperm[0]), tg, sb);
        #pragma unroll
        for (int ks = 0; ks < 2; ks++)
        #pragma unroll
        for (int h = 0; h < 2; h++) {
            int nt = 2 * ks + h;
            float2 w0 = s0[8 * nt + 2 * tg];
            float2 w1 = s0[8 * nt + 2 * tg + 1];
            float s0a = sa[2 * nt], s1a = sa[2 * nt + 1];
            float s0b = sb[2 * nt], s1b = sb[2 * nt + 1];
            split_pack(w0.x * s0a, w1.x * s1a, Amh[ks][2 * h],     Aml[ks][2 * h]);
            split_pack(w0.x * s0b, w1.x * s1b, Amh[ks][2 * h + 1], Aml[ks][2 * h + 1]);
            split_pack(w0.y * s0a * s0a, w1.y * s1a * s1a, Avh[ks][2 * h],     Avl[ks][2 * h]);
            split_pack(w0.y * s0b * s0b, w1.y * s1b * s1b, Avh[ks][2 * h + 1], Avl[ks][2 * h + 1]);
        }

        // prologue: mean MMAs of level 1 in flight
        issue_path(wbase, Amh, Aml, Dm);

        // ---- levels 1..7, staggered ----
        #pragma unroll 1
        for (int l = 1; l <= 7; l++) {
            u32 lb = wbase + (u32)((l - 1) * 8192);
            // var MMAs of level l (uses Av(l-1)); tensor busy through E_m below
            issue_path(lb + 4096, Avh, Avl, Dv);

            scales8(__ldg(xa + sperm[l]), tg, sa);
            scales8(__ldg(xb + sperm[l]), tg, sb);

            // E_m(l): Dm (drained) -> Am(l) or final mean accumulate
            if (l < 7) {
                #pragma unroll
                for (int ks = 0; ks < 2; ks++)
                #pragma unroll
                for (int h = 0; h < 2; h++) {
                    int nt = 2 * ks + h;
                    float s0a = sa[2 * nt], s1a = sa[2 * nt + 1];
                    float s0b = sb[2 * nt], s1b = sb[2 * nt + 1];
                    split_pack(Dm[nt][0] * s0a, Dm[nt][1] * s1a, Amh[ks][2 * h],     Aml[ks][2 * h]);
                    split_pack(Dm[nt][2] * s0b, Dm[nt][3] * s1b, Amh[ks][2 * h + 1], Aml[ks][2 * h + 1]);
                }
                // mean MMAs of level l+1; tensor busy through E_v below
                issue_path(lb + 8192, Amh, Aml, Dm);
            } else {
                smA = 0.f; smB = 0.f;
                #pragma unroll
                for (int nt = 0; nt < 4; nt++) {
                    smA += Dm[nt][0] * sa[2 * nt] + Dm[nt][1] * sa[2 * nt + 1];
                    smB += Dm[nt][2] * sb[2 * nt] + Dm[nt][3] * sb[2 * nt + 1];
                }
                smA += __shfl_xor_sync(0xffffffff, smA, 1); smA += __shfl_xor_sync(0xffffffff, smA, 2);
                smB += __shfl_xor_sync(0xffffffff, smB, 1); smB += __shfl_xor_sync(0xffffffff, smB, 2);
            }

            // E_v(l): Dv -> Av(l) or final var accumulate + stores
            if (l < 7) {
                #pragma unroll
                for (int ks = 0; ks < 2; ks++)
                #pragma unroll
                for (int h = 0; h < 2; h++) {
                    int nt = 2 * ks + h;
                    float s0a = sa[2 * nt], s1a = sa[2 * nt + 1];
                    float s0b = sb[2 * nt], s1b = sb[2 * nt + 1];
                    split_pack(Dv[nt][0] * s0a * s0a, Dv[nt][1] * s1a * s1a, Avh[ks][2 * h],     Avl[ks][2 * h]);
                    split_pack(Dv[nt][2] * s0b * s0b, Dv[nt][3] * s1b * s1b, Avh[ks][2 * h + 1], Avl[ks][2 * h + 1]);
                }
            } else {
                float svA = 0.f, svB = 0.f;
                #pragma unroll
                for (int nt = 0; nt < 4; nt++) {
                    float s0a = sa[2 * nt], s1a = sa[2 * nt + 1];
                    float s0b = sb[2 * nt], s1b = sb[2 * nt + 1];
                    svA += Dv[nt][0] * (s0a * s0a) + Dv[nt][1] * (s1a * s1a);
                    svB += Dv[nt][2] * (s0b * s0b) + Dv[nt][3] * (s1b * s1b);
                }
                svA += __shfl_xor_sync(0xffffffff, svA, 1); svA += __shfl_xor_sync(0xffffffff, svA, 2);
                svB += __shfl_xor_sync(0xffffffff, svB, 1); svB += __shfl_xor_sync(0xffffffff, svB, 2);
                if (tg == 0) {
                    g_pm[p * NSAMP + na] = smA;
                    g_pv[p * NSAMP + na] = svA * invp;
                    g_pm[p * NSAMP + nb] = smB;
                    g_pv[p * NSAMP + nb] = svB * invp;
                }
            }
        }
    }
}

// ---------------- reduction over permutations ----------------
__global__ void k_reduce(float* __restrict__ out) {
    int n = blockIdx.x * blockDim.x + threadIdx.x;
    float sm = 0.f, sv = 0.f;
    #pragma unroll
    for (int p = 0; p < PPERM; p++) {
        sm += g_pm[p * NSAMP + n];
        sv += g_pv[p * NSAMP + n];
    }
    out[2 * n]     = sm;
    out[2 * n + 1] = sv;
}

extern "C" void kernel_launch(void* const* d_in, const int* in_sizes, int n_in,
                              void* d_out, int out_size) {
    const float* X    = (const float*)d_in[0];
    const int*   perm = (const int*)  d_in[1];
    const float* wm0  = (const float*)d_in[2];
    const float* wmr  = (const float*)d_in[3];
    const float* wv0  = (const float*)d_in[4];
    const float* wvr  = (const float*)d_in[5];
    const float* pp   = (const float*)d_in[6];

    cudaFuncSetAttribute(k_main, cudaFuncAttributeMaxDynamicSharedMemorySize, 57344);
    // launch index 3 = k_main (ncu captures the 4th launch)
    k_sc2<<<1, 32>>>();
    k_prep_frag<<<(PPERM * 28672 + 255) / 256, 256>>>(wmr, wvr);
    k_prep0<<<(PPERM * 25 + 255) / 256, 256>>>(wm0, wv0);
    k_main<<<dim3(32, 32), 256, 57344>>>(X, perm, pp);
    k_reduce<<<NSAMP / 256, 256>>>((float*)d_out);
}